// round 1
// baseline (speedup 1.0000x reference)
#include <cuda_runtime.h>

#define NB     16     // batch
#define NT     256    // timesteps
#define NIN    6
#define NHID   256
#define NFEAT  64
#define NSTATE 64
#define NMOTOR 16
#define NUNF   6
#define EPSV   1e-8f

// scratch: state-independent sensory sums  [B,T,STATE]
__device__ float g_num[NB * NT * NSTATE];
__device__ float g_den[NB * NT * NSTATE];

__device__ __forceinline__ float sigm(float x) {
    float e = __expf(-x);
    return __fdividef(1.0f, 1.0f + e);
}

// ---------------------------------------------------------------------------
// Kernel 1: prenet (6->256 tanh ->64) + input affine + sensory synapse sums.
// One block per (b,t). Fully parallel: 4096 blocks x 256 threads.
// ---------------------------------------------------------------------------
__global__ __launch_bounds__(256)
void prenet_sensory(const float* __restrict__ x,
                    const float* __restrict__ pw1, const float* __restrict__ pb1,
                    const float* __restrict__ pw2, const float* __restrict__ pb2,
                    const float* __restrict__ input_w, const float* __restrict__ input_b,
                    const float* __restrict__ sw,  const float* __restrict__ smu,
                    const float* __restrict__ ssig, const float* __restrict__ serev)
{
    __shared__ float hidden[NHID];
    __shared__ float featsh[NFEAT];
    __shared__ float pn[4][NSTATE];
    __shared__ float pd[4][NSTATE];

    const int bt  = blockIdx.x;
    const int tid = threadIdx.x;
    const int j   = tid & 63;
    const int q   = tid >> 6;      // 0..3

    // phase A: hidden[h] = tanh(x . pw1[:,h] + pb1[h]), h = tid
    {
        float xl[NIN];
        #pragma unroll
        for (int k = 0; k < NIN; k++) xl[k] = x[bt * NIN + k];
        float s = pb1[tid];
        #pragma unroll
        for (int k = 0; k < NIN; k++) s = fmaf(xl[k], pw1[k * NHID + tid], s);
        hidden[tid] = tanhf(s);
    }
    __syncthreads();

    // phase B: feat[j] = hidden . pw2[:,j] + pb2[j]; 4-way split over h
    {
        float acc = 0.0f;
        const int h0 = q * 64;
        #pragma unroll
        for (int h = 0; h < 64; h++)
            acc = fmaf(hidden[h0 + h], pw2[(h0 + h) * NFEAT + j], acc);
        pn[q][j] = acc;
    }
    __syncthreads();
    if (tid < NFEAT) {
        float f = pn[0][tid] + pn[1][tid] + pn[2][tid] + pn[3][tid] + pb2[tid];
        f = fmaf(f, input_w[tid], input_b[tid]);
        featsh[tid] = f;
    }
    __syncthreads();

    // phase C: sensory sums over FEAT; 4 groups of 16 feats each
    {
        float np = 0.0f, dp = 0.0f;
        const int f0 = q * 16;
        #pragma unroll
        for (int fi = 0; fi < 16; fi++) {
            const int f   = f0 + fi;
            const int idx = f * NSTATE + j;
            float a = sw[idx] * sigm((featsh[f] - smu[idx]) * ssig[idx]);
            np = fmaf(a, serev[idx], np);
            dp += a;
        }
        pn[q][j] = np;
        pd[q][j] = dp;
    }
    __syncthreads();
    if (tid < NSTATE) {
        g_num[bt * NSTATE + tid] = pn[0][tid] + pn[1][tid] + pn[2][tid] + pn[3][tid];
        g_den[bt * NSTATE + tid] = pd[0][tid] + pd[1][tid] + pd[2][tid] + pd[3][tid];
    }
}

// ---------------------------------------------------------------------------
// Kernel 2: sequential LTC scan. One CTA per batch (16 CTAs), 512 threads.
// Thread (g,j): g = i-group (8 rows each), j = post neuron.
// All per-(i,j) synapse constants live in registers for the whole sequence.
// ---------------------------------------------------------------------------
__global__ __launch_bounds__(512, 1)
void ltc_scan(const float* __restrict__ w_,    const float* __restrict__ mu_,
              const float* __restrict__ sigma_, const float* __restrict__ erev_,
              const float* __restrict__ gleak,  const float* __restrict__ vleak,
              const float* __restrict__ cm,
              const float* __restrict__ ow,     const float* __restrict__ ob,
              float* __restrict__ out)
{
    __shared__ float vsh[NSTATE];
    __shared__ float pn[8][NSTATE];
    __shared__ float pd[8][NSTATE];

    const int b   = blockIdx.x;
    const int tid = threadIdx.x;
    const int j   = tid & 63;
    const int g   = tid >> 6;      // 0..7

    // per-thread synapse constants for rows i = g*8 .. g*8+7, column j
    float wv[8], we[8], sg[8], ms[8];
    #pragma unroll
    for (int k = 0; k < 8; k++) {
        const int i   = g * 8 + k;
        const int idx = i * NSTATE + j;
        wv[k] = w_[idx];
        we[k] = wv[k] * erev_[idx];
        sg[k] = sigma_[idx];
        ms[k] = mu_[idx] * sg[k];
    }

    float cm_t = 0.0f, gl = 0.0f, leak = 0.0f, owv = 0.0f, obv = 0.0f;
    if (tid < NSTATE) {
        cm_t = cm[tid] * (float)NUNF;
        gl   = gleak[tid];
        leak = gl * vleak[tid];
        vsh[tid] = 0.0f;
    }
    if (tid < NMOTOR) { owv = ow[tid]; obv = ob[tid]; }
    float vj = 0.0f;
    __syncthreads();

    const float* nb   = g_num + b * NT * NSTATE;
    const float* db   = g_den + b * NT * NSTATE;
    float*       outb = out   + b * NT * NMOTOR;

    for (int t = 0; t < NT; t++) {
        float ns = 0.0f, ds = 0.0f;
        if (tid < NSTATE) {
            ns = nb[t * NSTATE + tid];
            ds = db[t * NSTATE + tid];
        }

        #pragma unroll 1
        for (int u = 0; u < NUNF; u++) {
            float np = 0.0f, dp = 0.0f;
            #pragma unroll
            for (int k = 0; k < 8; k++) {
                float vi = vsh[g * 8 + k];                 // broadcast LDS
                float s  = sigm(fmaf(vi, sg[k], -ms[k]));  // sigmoid((v-mu)*sigma)
                np = fmaf(we[k], s, np);
                dp = fmaf(wv[k], s, dp);
            }
            pn[g][j] = np;
            pd[g][j] = dp;
            __syncthreads();
            if (tid < NSTATE) {
                float sn = 0.0f, sd = 0.0f;
                #pragma unroll
                for (int r = 0; r < 8; r++) { sn += pn[r][tid]; sd += pd[r][tid]; }
                float numer = cm_t * vj + leak + sn + ns;
                float denom = cm_t + gl + sd + ds + EPSV;
                vj = numer / denom;
                vsh[tid] = vj;
            }
            __syncthreads();
        }

        if (tid < NMOTOR)
            outb[t * NMOTOR + tid] = fmaf(vj, owv, obv);
    }
}

// ---------------------------------------------------------------------------
extern "C" void kernel_launch(void* const* d_in, const int* in_sizes, int n_in,
                              void* d_out, int out_size)
{
    const float* x        = (const float*)d_in[0];
    const float* pw1      = (const float*)d_in[1];
    const float* pb1      = (const float*)d_in[2];
    const float* pw2      = (const float*)d_in[3];
    const float* pb2      = (const float*)d_in[4];
    const float* input_w  = (const float*)d_in[5];
    const float* input_b  = (const float*)d_in[6];
    const float* sw       = (const float*)d_in[7];
    const float* smu      = (const float*)d_in[8];
    const float* ssig     = (const float*)d_in[9];
    const float* serev    = (const float*)d_in[10];
    const float* w_       = (const float*)d_in[11];
    const float* mu_      = (const float*)d_in[12];
    const float* sigma_   = (const float*)d_in[13];
    const float* erev_    = (const float*)d_in[14];
    const float* gleak    = (const float*)d_in[15];
    const float* vleak    = (const float*)d_in[16];
    const float* cm       = (const float*)d_in[17];
    const float* ow       = (const float*)d_in[18];
    const float* ob       = (const float*)d_in[19];
    float* out = (float*)d_out;

    prenet_sensory<<<NB * NT, 256>>>(x, pw1, pb1, pw2, pb2, input_w, input_b,
                                     sw, smu, ssig, serev);
    ltc_scan<<<NB, 512>>>(w_, mu_, sigma_, erev_, gleak, vleak, cm, ow, ob, out);
}

// round 2
// speedup vs baseline: 1.3477x; 1.3477x over previous
#include <cuda_runtime.h>

#define NB     16     // batch
#define NT     256    // timesteps
#define NIN    6
#define NHID   256
#define NFEAT  64
#define NSTATE 64
#define NMOTOR 16
#define NUNF   6
#define EPSV   1e-8f

// scratch: state-independent sensory sums  [B,T,STATE]
__device__ float g_num[NB * NT * NSTATE];
__device__ float g_den[NB * NT * NSTATE];

__device__ __forceinline__ float sigm(float x) {
    float e = __expf(-x);
    return __fdividef(1.0f, 1.0f + e);
}

__device__ __forceinline__ float tanh_fast(float x) {
    float y;
    asm("tanh.approx.f32 %0, %1;" : "=f"(y) : "f"(x));
    return y;
}

// ---------------------------------------------------------------------------
// Kernel 1: prenet (6->256 tanh ->64) + input affine + sensory synapse sums.
// One block per (b,t). Fully parallel: 4096 blocks x 256 threads.
// ---------------------------------------------------------------------------
__global__ __launch_bounds__(256)
void prenet_sensory(const float* __restrict__ x,
                    const float* __restrict__ pw1, const float* __restrict__ pb1,
                    const float* __restrict__ pw2, const float* __restrict__ pb2,
                    const float* __restrict__ input_w, const float* __restrict__ input_b,
                    const float* __restrict__ sw,  const float* __restrict__ smu,
                    const float* __restrict__ ssig, const float* __restrict__ serev)
{
    __shared__ float hidden[NHID];
    __shared__ float featsh[NFEAT];
    __shared__ float pn[4][NSTATE];
    __shared__ float pd[4][NSTATE];

    const int bt  = blockIdx.x;
    const int tid = threadIdx.x;
    const int j   = tid & 63;
    const int q   = tid >> 6;      // 0..3

    // phase A: hidden[h] = tanh(x . pw1[:,h] + pb1[h]), h = tid
    {
        float xl[NIN];
        #pragma unroll
        for (int k = 0; k < NIN; k++) xl[k] = x[bt * NIN + k];
        float s = pb1[tid];
        #pragma unroll
        for (int k = 0; k < NIN; k++) s = fmaf(xl[k], pw1[k * NHID + tid], s);
        hidden[tid] = tanhf(s);
    }
    __syncthreads();

    // phase B: feat[j] = hidden . pw2[:,j] + pb2[j]; 4-way split over h
    {
        float acc = 0.0f;
        const int h0 = q * 64;
        #pragma unroll
        for (int h = 0; h < 64; h++)
            acc = fmaf(hidden[h0 + h], pw2[(h0 + h) * NFEAT + j], acc);
        pn[q][j] = acc;
    }
    __syncthreads();
    if (tid < NFEAT) {
        float f = pn[0][tid] + pn[1][tid] + pn[2][tid] + pn[3][tid] + pb2[tid];
        f = fmaf(f, input_w[tid], input_b[tid]);
        featsh[tid] = f;
    }
    __syncthreads();

    // phase C: sensory sums over FEAT; 4 groups of 16 feats each
    {
        float np = 0.0f, dp = 0.0f;
        const int f0 = q * 16;
        #pragma unroll
        for (int fi = 0; fi < 16; fi++) {
            const int f   = f0 + fi;
            const int idx = f * NSTATE + j;
            float a = sw[idx] * sigm((featsh[f] - smu[idx]) * ssig[idx]);
            np = fmaf(a, serev[idx], np);
            dp += a;
        }
        pn[q][j] = np;
        pd[q][j] = dp;
    }
    __syncthreads();
    if (tid < NSTATE) {
        g_num[bt * NSTATE + tid] = pn[0][tid] + pn[1][tid] + pn[2][tid] + pn[3][tid];
        g_den[bt * NSTATE + tid] = pd[0][tid] + pd[1][tid] + pd[2][tid] + pd[3][tid];
    }
}

// ---------------------------------------------------------------------------
// Kernel 2: sequential LTC scan. One CTA per batch (16 CTAs), 512 threads.
// Layout: j = tid>>3 (post neuron), g = tid&7 (row group of 8 pre neurons).
// Cross-group reduction = intra-warp shfl.bfly (lanes differing in bits 0..2).
// sigmoid via tanh.approx with 0.5-factors folded into weights.
// Double-buffered v state -> ONE __syncthreads per unfold.
// ---------------------------------------------------------------------------
__global__ __launch_bounds__(512, 1)
void ltc_scan(const float* __restrict__ w_,    const float* __restrict__ mu_,
              const float* __restrict__ sigma_, const float* __restrict__ erev_,
              const float* __restrict__ gleak,  const float* __restrict__ vleak,
              const float* __restrict__ cm,
              const float* __restrict__ ow,     const float* __restrict__ ob,
              float* __restrict__ out)
{
    __shared__ __align__(16) float vsh[2][NSTATE];

    const int b   = blockIdx.x;
    const int tid = threadIdx.x;
    const int j   = tid >> 3;      // 0..63 post neuron
    const int g   = tid & 7;       // 0..7 row group

    // per-thread synapse constants for rows i = g*8..g*8+7, column j.
    // sigmoid(x) = 0.5*tanh(0.5x) + 0.5 ; fold 0.5's:
    //   arg_k = v_i * (0.5*sigma) - 0.5*mu*sigma
    //   np    = sum 0.5*w*erev*(tanh+1) = swe + sum hwe*tanh
    float hs[8], hb[8], hwe[8], hwv[8];
    float swe = 0.0f, swv = 0.0f;
    #pragma unroll
    for (int k = 0; k < 8; k++) {
        const int i   = g * 8 + k;
        const int idx = i * NSTATE + j;
        float wv = w_[idx];
        float er = erev_[idx];
        float sgv = sigma_[idx];
        float muv = mu_[idx];
        hwv[k] = 0.5f * wv;
        hwe[k] = 0.5f * wv * er;
        hs[k]  = 0.5f * sgv;
        hb[k]  = 0.5f * muv * sgv;
        swe += hwe[k];
        swv += hwv[k];
    }

    // per-j scalars (replicated across the 8 lanes sharing j)
    const float cm_t = cm[j] * (float)NUNF;
    const float gl   = gleak[j];
    const float leak = gl * vleak[j];
    float owv = 0.0f, obv = 0.0f;
    if (j < NMOTOR) { owv = ow[j]; obv = ob[j]; }

    if (tid < NSTATE) vsh[0][tid] = 0.0f;
    float vj = 0.0f;
    __syncthreads();

    const float* nb   = g_num + b * NT * NSTATE;
    const float* db   = g_den + b * NT * NSTATE;
    float*       outb = out   + b * NT * NMOTOR;

    int cur = 0;
    for (int t = 0; t < NT; t++) {
        const float ns = nb[t * NSTATE + j];
        const float ds = db[t * NSTATE + j];

        #pragma unroll
        for (int u = 0; u < NUNF; u++) {
            // load my 8 pre-neuron voltages (two LDS.128, broadcast-friendly)
            float4 va = *reinterpret_cast<const float4*>(&vsh[cur][g * 8]);
            float4 vb = *reinterpret_cast<const float4*>(&vsh[cur][g * 8 + 4]);
            float vv[8] = {va.x, va.y, va.z, va.w, vb.x, vb.y, vb.z, vb.w};

            float np = swe, dp = swv;
            #pragma unroll
            for (int k = 0; k < 8; k++) {
                float th = tanh_fast(fmaf(vv[k], hs[k], -hb[k]));
                np = fmaf(hwe[k], th, np);
                dp = fmaf(hwv[k], th, dp);
            }
            // reduce across the 8 lanes sharing j (lane bits 0..2)
            np += __shfl_xor_sync(0xffffffffu, np, 1);
            dp += __shfl_xor_sync(0xffffffffu, dp, 1);
            np += __shfl_xor_sync(0xffffffffu, np, 2);
            dp += __shfl_xor_sync(0xffffffffu, dp, 2);
            np += __shfl_xor_sync(0xffffffffu, np, 4);
            dp += __shfl_xor_sync(0xffffffffu, dp, 4);

            float numer = fmaf(cm_t, vj, leak) + np + ns;
            float denom = cm_t + gl + dp + ds + EPSV;
            vj = __fdividef(numer, denom);

            if (g == 0) vsh[cur ^ 1][j] = vj;   // write OTHER buffer: no read/write hazard
            __syncthreads();
            cur ^= 1;
        }

        if (j < NMOTOR && g == 0)
            outb[t * NMOTOR + j] = fmaf(vj, owv, obv);
    }
}

// ---------------------------------------------------------------------------
extern "C" void kernel_launch(void* const* d_in, const int* in_sizes, int n_in,
                              void* d_out, int out_size)
{
    const float* x        = (const float*)d_in[0];
    const float* pw1      = (const float*)d_in[1];
    const float* pb1      = (const float*)d_in[2];
    const float* pw2      = (const float*)d_in[3];
    const float* pb2      = (const float*)d_in[4];
    const float* input_w  = (const float*)d_in[5];
    const float* input_b  = (const float*)d_in[6];
    const float* sw       = (const float*)d_in[7];
    const float* smu      = (const float*)d_in[8];
    const float* ssig     = (const float*)d_in[9];
    const float* serev    = (const float*)d_in[10];
    const float* w_       = (const float*)d_in[11];
    const float* mu_      = (const float*)d_in[12];
    const float* sigma_   = (const float*)d_in[13];
    const float* erev_    = (const float*)d_in[14];
    const float* gleak    = (const float*)d_in[15];
    const float* vleak    = (const float*)d_in[16];
    const float* cm       = (const float*)d_in[17];
    const float* ow       = (const float*)d_in[18];
    const float* ob       = (const float*)d_in[19];
    float* out = (float*)d_out;

    prenet_sensory<<<NB * NT, 256>>>(x, pw1, pb1, pw2, pb2, input_w, input_b,
                                     sw, smu, ssig, serev);
    ltc_scan<<<NB, 512>>>(w_, mu_, sigma_, erev_, gleak, vleak, cm, ow, ob, out);
}

// round 3
// speedup vs baseline: 1.4139x; 1.0491x over previous
#include <cuda_runtime.h>

#define NB     16     // batch
#define NT     256    // timesteps
#define NIN    6
#define NHID   256
#define NFEAT  64
#define NSTATE 64
#define NMOTOR 16
#define NUNF   6
#define EPSV   1e-8f

// scratch: state-independent sensory sums  [B,T,STATE]
__device__ float g_num[NB * NT * NSTATE];
__device__ float g_den[NB * NT * NSTATE];

__device__ __forceinline__ float sigm(float x) {
    float e = __expf(-x);
    return __fdividef(1.0f, 1.0f + e);
}

__device__ __forceinline__ float tanh_fast(float x) {
    float y;
    asm("tanh.approx.f32 %0, %1;" : "=f"(y) : "f"(x));
    return y;
}

// ---------------------------------------------------------------------------
// Kernel 1: prenet (6->256 tanh ->64) + input affine + sensory synapse sums.
// One block per (b,t). Fully parallel: 4096 blocks x 256 threads.
// ---------------------------------------------------------------------------
__global__ __launch_bounds__(256)
void prenet_sensory(const float* __restrict__ x,
                    const float* __restrict__ pw1, const float* __restrict__ pb1,
                    const float* __restrict__ pw2, const float* __restrict__ pb2,
                    const float* __restrict__ input_w, const float* __restrict__ input_b,
                    const float* __restrict__ sw,  const float* __restrict__ smu,
                    const float* __restrict__ ssig, const float* __restrict__ serev)
{
    __shared__ float hidden[NHID];
    __shared__ float featsh[NFEAT];
    __shared__ float pn[4][NSTATE];
    __shared__ float pd[4][NSTATE];

    const int bt  = blockIdx.x;
    const int tid = threadIdx.x;
    const int j   = tid & 63;
    const int q   = tid >> 6;      // 0..3

    // phase A: hidden[h] = tanh(x . pw1[:,h] + pb1[h]), h = tid
    {
        float xl[NIN];
        #pragma unroll
        for (int k = 0; k < NIN; k++) xl[k] = x[bt * NIN + k];
        float s = pb1[tid];
        #pragma unroll
        for (int k = 0; k < NIN; k++) s = fmaf(xl[k], pw1[k * NHID + tid], s);
        hidden[tid] = tanhf(s);
    }
    __syncthreads();

    // phase B: feat[j] = hidden . pw2[:,j] + pb2[j]; 4-way split over h
    {
        float acc = 0.0f;
        const int h0 = q * 64;
        #pragma unroll
        for (int h = 0; h < 64; h++)
            acc = fmaf(hidden[h0 + h], pw2[(h0 + h) * NFEAT + j], acc);
        pn[q][j] = acc;
    }
    __syncthreads();
    if (tid < NFEAT) {
        float f = pn[0][tid] + pn[1][tid] + pn[2][tid] + pn[3][tid] + pb2[tid];
        f = fmaf(f, input_w[tid], input_b[tid]);
        featsh[tid] = f;
    }
    __syncthreads();

    // phase C: sensory sums over FEAT; 4 groups of 16 feats each
    {
        float np = 0.0f, dp = 0.0f;
        const int f0 = q * 16;
        #pragma unroll
        for (int fi = 0; fi < 16; fi++) {
            const int f   = f0 + fi;
            const int idx = f * NSTATE + j;
            float a = sw[idx] * sigm((featsh[f] - smu[idx]) * ssig[idx]);
            np = fmaf(a, serev[idx], np);
            dp += a;
        }
        pn[q][j] = np;
        pd[q][j] = dp;
    }
    __syncthreads();
    if (tid < NSTATE) {
        g_num[bt * NSTATE + tid] = pn[0][tid] + pn[1][tid] + pn[2][tid] + pn[3][tid];
        g_den[bt * NSTATE + tid] = pd[0][tid] + pd[1][tid] + pd[2][tid] + pd[3][tid];
    }
}

// ---------------------------------------------------------------------------
// Kernel 2: sequential LTC scan. One CTA per batch (16 CTAs), 256 threads.
// Layout: j = tid>>2 (post neuron), g = tid&3 (row group of 16 pre neurons).
// Cross-group reduction = 2-level shfl.bfly over lane bits 0..1.
// sigmoid via tanh.approx with 0.5-factors folded into weights.
// Double-buffered v state (compile-time buffer index), ONE barrier per unfold.
// ns/ds for t+1 prefetched so the L2-hit LDG hides behind the 6 unfolds.
// ---------------------------------------------------------------------------
__global__ __launch_bounds__(256, 1)
void ltc_scan(const float* __restrict__ w_,    const float* __restrict__ mu_,
              const float* __restrict__ sigma_, const float* __restrict__ erev_,
              const float* __restrict__ gleak,  const float* __restrict__ vleak,
              const float* __restrict__ cm,
              const float* __restrict__ ow,     const float* __restrict__ ob,
              float* __restrict__ out)
{
    __shared__ __align__(16) float vsh[2][NSTATE];

    const int b   = blockIdx.x;
    const int tid = threadIdx.x;
    const int j   = tid >> 2;      // 0..63 post neuron
    const int g   = tid & 3;       // 0..3 row group (16 rows each)

    // per-thread synapse constants for rows i = g*16..g*16+15, column j.
    // sigmoid(x) = 0.5*tanh(0.5x) + 0.5 ; fold 0.5's:
    //   arg_k = v_i * (0.5*sigma) - 0.5*mu*sigma
    //   np    = sum 0.5*w*erev*(tanh+1) = swe + sum hwe*tanh
    float hs[16], hb[16], hwe[16], hwv[16];
    float swe = 0.0f, swv = 0.0f;
    #pragma unroll
    for (int k = 0; k < 16; k++) {
        const int i   = g * 16 + k;
        const int idx = i * NSTATE + j;
        float wv  = w_[idx];
        float er  = erev_[idx];
        float sgv = sigma_[idx];
        float muv = mu_[idx];
        hwv[k] = 0.5f * wv;
        hwe[k] = 0.5f * wv * er;
        hs[k]  = 0.5f * sgv;
        hb[k]  = 0.5f * muv * sgv;
        swe += hwe[k];
        swv += hwv[k];
    }

    // per-j scalars (replicated across the 4 lanes sharing j)
    const float cm_t = cm[j] * (float)NUNF;
    const float gl   = gleak[j];
    const float leak = gl * vleak[j];
    const float denc = cm_t + gl + EPSV;   // constant part of denominator
    float owv = 0.0f, obv = 0.0f;
    if (j < NMOTOR) { owv = ow[j]; obv = ob[j]; }

    if (tid < NSTATE) vsh[0][tid] = 0.0f;
    float vj = 0.0f;
    __syncthreads();

    const float* nb   = g_num + b * NT * NSTATE;
    const float* db   = g_den + b * NT * NSTATE;
    float*       outb = out   + b * NT * NMOTOR;

    float ns = nb[j];
    float ds = db[j];

    for (int t = 0; t < NT; t++) {
        // issue next-t loads immediately; consumed only after 6 unfolds
        const int tn = (t + 1 < NT) ? (t + 1) : t;
        float ns_next = nb[tn * NSTATE + j];
        float ds_next = db[tn * NSTATE + j];

        const float nsl = ns + leak;   // numerator constant for this t
        const float dsl = ds + denc;   // denominator constant for this t

        #pragma unroll
        for (int u = 0; u < NUNF; u++) {
            const int cur = u & 1;
            // load my 16 pre-neuron voltages (four LDS.128, broadcast-friendly)
            float vv[16];
            #pragma unroll
            for (int c = 0; c < 4; c++) {
                float4 vq = *reinterpret_cast<const float4*>(&vsh[cur][g * 16 + c * 4]);
                vv[c * 4 + 0] = vq.x; vv[c * 4 + 1] = vq.y;
                vv[c * 4 + 2] = vq.z; vv[c * 4 + 3] = vq.w;
            }

            // 4 partial accumulators each to keep FMA chains short
            float np0 = swe, np1 = 0.f, np2 = 0.f, np3 = 0.f;
            float dp0 = swv, dp1 = 0.f, dp2 = 0.f, dp3 = 0.f;
            #pragma unroll
            for (int k = 0; k < 16; k += 4) {
                float t0 = tanh_fast(fmaf(vv[k + 0], hs[k + 0], -hb[k + 0]));
                float t1 = tanh_fast(fmaf(vv[k + 1], hs[k + 1], -hb[k + 1]));
                float t2 = tanh_fast(fmaf(vv[k + 2], hs[k + 2], -hb[k + 2]));
                float t3 = tanh_fast(fmaf(vv[k + 3], hs[k + 3], -hb[k + 3]));
                np0 = fmaf(hwe[k + 0], t0, np0);
                np1 = fmaf(hwe[k + 1], t1, np1);
                np2 = fmaf(hwe[k + 2], t2, np2);
                np3 = fmaf(hwe[k + 3], t3, np3);
                dp0 = fmaf(hwv[k + 0], t0, dp0);
                dp1 = fmaf(hwv[k + 1], t1, dp1);
                dp2 = fmaf(hwv[k + 2], t2, dp2);
                dp3 = fmaf(hwv[k + 3], t3, dp3);
            }
            float dp = (dp0 + dp1) + (dp2 + dp3);
            float np = (np0 + np1) + (np2 + np3);

            // reduce across the 4 lanes sharing j (lane bits 0..1); dp first so
            // the rcp can start while np finishes
            dp += __shfl_xor_sync(0xffffffffu, dp, 1);
            np += __shfl_xor_sync(0xffffffffu, np, 1);
            dp += __shfl_xor_sync(0xffffffffu, dp, 2);
            np += __shfl_xor_sync(0xffffffffu, np, 2);

            float denom = dp + dsl;
            float numer = fmaf(cm_t, vj, np + nsl);
            vj = __fdividef(numer, denom);

            if (g == 0) vsh[cur ^ 1][j] = vj;   // write OTHER buffer: no hazard
            __syncthreads();
        }

        if (j < NMOTOR && g == 0)
            outb[t * NMOTOR + j] = fmaf(vj, owv, obv);

        ns = ns_next;
        ds = ds_next;
    }
}

// ---------------------------------------------------------------------------
extern "C" void kernel_launch(void* const* d_in, const int* in_sizes, int n_in,
                              void* d_out, int out_size)
{
    const float* x        = (const float*)d_in[0];
    const float* pw1      = (const float*)d_in[1];
    const float* pb1      = (const float*)d_in[2];
    const float* pw2      = (const float*)d_in[3];
    const float* pb2      = (const float*)d_in[4];
    const float* input_w  = (const float*)d_in[5];
    const float* input_b  = (const float*)d_in[6];
    const float* sw       = (const float*)d_in[7];
    const float* smu      = (const float*)d_in[8];
    const float* ssig     = (const float*)d_in[9];
    const float* serev    = (const float*)d_in[10];
    const float* w_       = (const float*)d_in[11];
    const float* mu_      = (const float*)d_in[12];
    const float* sigma_   = (const float*)d_in[13];
    const float* erev_    = (const float*)d_in[14];
    const float* gleak    = (const float*)d_in[15];
    const float* vleak    = (const float*)d_in[16];
    const float* cm       = (const float*)d_in[17];
    const float* ow       = (const float*)d_in[18];
    const float* ob       = (const float*)d_in[19];
    float* out = (float*)d_out;

    prenet_sensory<<<NB * NT, 256>>>(x, pw1, pb1, pw2, pb2, input_w, input_b,
                                     sw, smu, ssig, serev);
    ltc_scan<<<NB, 256>>>(w_, mu_, sigma_, erev_, gleak, vleak, cm, ow, ob, out);
}

// round 5
// speedup vs baseline: 1.7249x; 1.2200x over previous
#include <cuda_runtime.h>

#define NB     16     // batch
#define NT     256    // timesteps
#define NIN    6
#define NHID   256
#define NFEAT  64
#define NSTATE 64
#define NMOTOR 16
#define NUNF   6
#define EPSV   1e-8f

// scratch: state-independent sensory sums  [B,T,STATE]
__device__ float g_num[NB * NT * NSTATE];
__device__ float g_den[NB * NT * NSTATE];

__device__ __forceinline__ float tanh_fast(float x) {
    float y;
    asm("tanh.approx.f32 %0, %1;" : "=f"(y) : "f"(x));
    return y;
}

// ---------------------------------------------------------------------------
// Kernel 1: prenet (6->256 tanh ->64) + input affine + sensory synapse sums.
// One block per (b,t). Fully parallel: 4096 blocks x 256 threads.
// All transcendentals via single-MUFU tanh.approx.
// ---------------------------------------------------------------------------
__global__ __launch_bounds__(256)
void prenet_sensory(const float* __restrict__ x,
                    const float* __restrict__ pw1, const float* __restrict__ pb1,
                    const float* __restrict__ pw2, const float* __restrict__ pb2,
                    const float* __restrict__ input_w, const float* __restrict__ input_b,
                    const float* __restrict__ sw,  const float* __restrict__ smu,
                    const float* __restrict__ ssig, const float* __restrict__ serev)
{
    __shared__ float hidden[NHID];
    __shared__ float featsh[NFEAT];
    __shared__ float pn[4][NSTATE];
    __shared__ float pd[4][NSTATE];

    const int bt  = blockIdx.x;
    const int tid = threadIdx.x;
    const int j   = tid & 63;
    const int q   = tid >> 6;      // 0..3

    // phase A: hidden[h] = tanh(x . pw1[:,h] + pb1[h]), h = tid
    {
        float xl[NIN];
        #pragma unroll
        for (int k = 0; k < NIN; k++) xl[k] = x[bt * NIN + k];
        float s = pb1[tid];
        #pragma unroll
        for (int k = 0; k < NIN; k++) s = fmaf(xl[k], pw1[k * NHID + tid], s);
        hidden[tid] = tanh_fast(s);
    }
    __syncthreads();

    // phase B: feat[j] = hidden . pw2[:,j] + pb2[j]; 4-way split over h
    {
        float acc = 0.0f;
        const int h0 = q * 64;
        #pragma unroll
        for (int h = 0; h < 64; h++)
            acc = fmaf(hidden[h0 + h], pw2[(h0 + h) * NFEAT + j], acc);
        pn[q][j] = acc;
    }
    __syncthreads();
    if (tid < NFEAT) {
        float f = pn[0][tid] + pn[1][tid] + pn[2][tid] + pn[3][tid] + pb2[tid];
        f = fmaf(f, input_w[tid], input_b[tid]);
        featsh[tid] = f;
    }
    __syncthreads();

    // phase C: sensory sums over FEAT; 4 groups of 16 feats each.
    // sigmoid(z) = 0.5*tanh(0.5 z)+0.5 ; a = sw*sigmoid = fma(0.5*sw, th, 0.5*sw)
    {
        float np = 0.0f, dp = 0.0f;
        const int f0 = q * 16;
        #pragma unroll
        for (int fi = 0; fi < 16; fi++) {
            const int f   = f0 + fi;
            const int idx = f * NSTATE + j;
            float hswv = 0.5f * sw[idx];
            float th = tanh_fast(0.5f * (featsh[f] - smu[idx]) * ssig[idx]);
            float a  = fmaf(hswv, th, hswv);
            np = fmaf(a, serev[idx], np);
            dp += a;
        }
        pn[q][j] = np;
        pd[q][j] = dp;
    }
    __syncthreads();
    if (tid < NSTATE) {
        g_num[bt * NSTATE + tid] = pn[0][tid] + pn[1][tid] + pn[2][tid] + pn[3][tid];
        g_den[bt * NSTATE + tid] = pd[0][tid] + pd[1][tid] + pd[2][tid] + pd[3][tid];
    }
}

// ---------------------------------------------------------------------------
// Kernel 2: sequential LTC scan. One CTA per batch (16 CTAs), 128 threads
// (= 4 warps, exactly one per SMSP: densest MUFU packing, minimal barrier).
// Layout: j = tid>>1 (post neuron), g = tid&1 (row group of 32 pre neurons).
// Cross-group reduction = ONE shfl.bfly level (lane bit 0).
// sigmoid via tanh.approx with 0.5-factors folded into weights.
// Double-buffered v state, one barrier per unfold, next-t LDG prefetched.
// ---------------------------------------------------------------------------
__global__ __launch_bounds__(128, 1)
void ltc_scan(const float* __restrict__ w_,    const float* __restrict__ mu_,
              const float* __restrict__ sigma_, const float* __restrict__ erev_,
              const float* __restrict__ gleak,  const float* __restrict__ vleak,
              const float* __restrict__ cm,
              const float* __restrict__ ow,     const float* __restrict__ ob,
              float* __restrict__ out)
{
    __shared__ __align__(16) float vsh[2][NSTATE];

    const int b   = blockIdx.x;
    const int tid = threadIdx.x;
    const int j   = tid >> 1;      // 0..63 post neuron
    const int g   = tid & 1;       // 0..1 row group (32 rows each)

    // per-thread synapse constants for rows i = g*32..g*32+31, column j.
    //   arg_k = v_i * (0.5*sigma) - 0.5*mu*sigma
    //   np    = swe + sum hwe*tanh ,  dp = swv + sum hwv*tanh
    float hs[32], hb[32], hwe[32], hwv[32];
    float swe = 0.0f, swv = 0.0f;
    #pragma unroll
    for (int k = 0; k < 32; k++) {
        const int i   = g * 32 + k;
        const int idx = i * NSTATE + j;
        float wv  = w_[idx];
        float er  = erev_[idx];
        float sgv = sigma_[idx];
        float muv = mu_[idx];
        hwv[k] = 0.5f * wv;
        hwe[k] = 0.5f * wv * er;
        hs[k]  = 0.5f * sgv;
        hb[k]  = 0.5f * muv * sgv;
        swe += hwe[k];
        swv += hwv[k];
    }

    // per-j scalars (replicated across the 2 lanes sharing j)
    const float cm_t = cm[j] * (float)NUNF;
    const float gl   = gleak[j];
    const float leak = gl * vleak[j];
    const float denc = cm_t + gl + EPSV;   // constant part of denominator
    float owv = 0.0f, obv = 0.0f;
    if (j < NMOTOR) { owv = ow[j]; obv = ob[j]; }

    if (tid < NSTATE) vsh[0][tid] = 0.0f;
    float vj = 0.0f;
    __syncthreads();

    const float* nb   = g_num + b * NT * NSTATE;
    const float* db   = g_den + b * NT * NSTATE;
    float*       outb = out   + b * NT * NMOTOR;

    float ns = nb[j];
    float ds = db[j];

    for (int t = 0; t < NT; t++) {
        // issue next-t loads immediately; consumed only after 6 unfolds
        const int tn = (t + 1 < NT) ? (t + 1) : t;
        float ns_next = nb[tn * NSTATE + j];
        float ds_next = db[tn * NSTATE + j];

        const float nsl = ns + leak;   // numerator constant for this t
        const float dsl = ds + denc;   // denominator constant for this t

        #pragma unroll
        for (int u = 0; u < NUNF; u++) {
            const int cur = u & 1;

            // 4 partial accumulators each; consume v in float4 chunks
            float np0 = swe, np1 = 0.f, np2 = 0.f, np3 = 0.f;
            float dp0 = swv, dp1 = 0.f, dp2 = 0.f, dp3 = 0.f;
            #pragma unroll
            for (int c = 0; c < 8; c++) {
                float4 vq = *reinterpret_cast<const float4*>(&vsh[cur][g * 32 + c * 4]);
                const int k = c * 4;
                float t0 = tanh_fast(fmaf(vq.x, hs[k + 0], -hb[k + 0]));
                float t1 = tanh_fast(fmaf(vq.y, hs[k + 1], -hb[k + 1]));
                float t2 = tanh_fast(fmaf(vq.z, hs[k + 2], -hb[k + 2]));
                float t3 = tanh_fast(fmaf(vq.w, hs[k + 3], -hb[k + 3]));
                np0 = fmaf(hwe[k + 0], t0, np0);
                np1 = fmaf(hwe[k + 1], t1, np1);
                np2 = fmaf(hwe[k + 2], t2, np2);
                np3 = fmaf(hwe[k + 3], t3, np3);
                dp0 = fmaf(hwv[k + 0], t0, dp0);
                dp1 = fmaf(hwv[k + 1], t1, dp1);
                dp2 = fmaf(hwv[k + 2], t2, dp2);
                dp3 = fmaf(hwv[k + 3], t3, dp3);
            }
            float dp = (dp0 + dp1) + (dp2 + dp3);
            float np = (np0 + np1) + (np2 + np3);

            // reduce across the 2 lanes sharing j (lane bit 0); dp first so the
            // reciprocal can start while np finishes
            dp += __shfl_xor_sync(0xffffffffu, dp, 1);
            np += __shfl_xor_sync(0xffffffffu, np, 1);

            float denom = dp + dsl;
            float numer = fmaf(cm_t, vj, np + nsl);
            vj = __fdividef(numer, denom);

            if (g == 0) vsh[cur ^ 1][j] = vj;   // write OTHER buffer: no hazard
            __syncthreads();
        }

        if (j < NMOTOR && g == 0)
            outb[t * NMOTOR + j] = fmaf(vj, owv, obv);

        ns = ns_next;
        ds = ds_next;
    }
}

// ---------------------------------------------------------------------------
extern "C" void kernel_launch(void* const* d_in, const int* in_sizes, int n_in,
                              void* d_out, int out_size)
{
    const float* x        = (const float*)d_in[0];
    const float* pw1      = (const float*)d_in[1];
    const float* pb1      = (const float*)d_in[2];
    const float* pw2      = (const float*)d_in[3];
    const float* pb2      = (const float*)d_in[4];
    const float* input_w  = (const float*)d_in[5];
    const float* input_b  = (const float*)d_in[6];
    const float* sw       = (const float*)d_in[7];
    const float* smu      = (const float*)d_in[8];
    const float* ssig     = (const float*)d_in[9];
    const float* serev    = (const float*)d_in[10];
    const float* w_       = (const float*)d_in[11];
    const float* mu_      = (const float*)d_in[12];
    const float* sigma_   = (const float*)d_in[13];
    const float* erev_    = (const float*)d_in[14];
    const float* gleak    = (const float*)d_in[15];
    const float* vleak    = (const float*)d_in[16];
    const float* cm       = (const float*)d_in[17];
    const float* ow       = (const float*)d_in[18];
    const float* ob       = (const float*)d_in[19];
    float* out = (float*)d_out;

    prenet_sensory<<<NB * NT, 256>>>(x, pw1, pb1, pw2, pb2, input_w, input_b,
                                     sw, smu, ssig, serev);
    ltc_scan<<<NB, 128>>>(w_, mu_, sigma_, erev_, gleak, vleak, cm, ow, ob, out);
}